// round 7
// baseline (speedup 1.0000x reference)
#include <cuda_runtime.h>

constexpr int B_   = 2;
constexpr int SQ_  = 2048;
constexpr int SKV_ = 2048;
constexpr int H_   = 1024;
constexpr int NH_  = 16;
constexpr int HD_  = 64;

__device__ float g_q[(size_t)B_ * SQ_ * H_];
__device__ float g_k[(size_t)B_ * SKV_ * H_];
__device__ float g_v[(size_t)B_ * SKV_ * H_];
__device__ float g_ctx[(size_t)B_ * SQ_ * H_];

__device__ __forceinline__ unsigned f2tf(float f) {
    unsigned u; asm("cvt.rna.tf32.f32 %0, %1;" : "=r"(u) : "f"(f)); return u;
}
__device__ __forceinline__ void mma8(float d[4], const unsigned a[4], const unsigned b[2]) {
    asm volatile(
        "mma.sync.aligned.m16n8k8.row.col.f32.tf32.tf32.f32 "
        "{%0,%1,%2,%3},{%4,%5,%6,%7},{%8,%9},{%0,%1,%2,%3};"
        : "+f"(d[0]), "+f"(d[1]), "+f"(d[2]), "+f"(d[3])
        : "r"(a[0]), "r"(a[1]), "r"(a[2]), "r"(a[3]), "r"(b[0]), "r"(b[1]));
}

// k-pair permuted packing: group [d0..d7] stored as [d0,d4,d1,d5,d2,d6,d3,d7]
// so fragment pair (kk+tg, kk+tg+4) = one LDS.64 at word kk + 2*tg.
#define PACK_HI(v0, v1) make_uint4(f2tf((v0).x), f2tf((v1).x), f2tf((v0).y), f2tf((v1).y))
#define PACK_LO(v0, v1) make_uint4(f2tf((v0).z), f2tf((v1).z), f2tf((v0).w), f2tf((v1).w))

// ---------------- projection GEMM: C = A @ W^T + bias ----------------------
// 128x128 tile, BK=16, double-buffered, permuted-vectorized fragment loads.
__device__ __forceinline__ void gemm_body(
    const float* __restrict__ A, const float* __restrict__ W,
    const float* __restrict__ bias, float* __restrict__ C,
    int M, int N, int K)
{
    __shared__ __align__(16) unsigned As[2][128][20];
    __shared__ __align__(16) unsigned Bs[2][128][20];

    const int tid = threadIdx.x;
    const int wid = tid >> 5, lane = tid & 31;
    const int g = lane >> 2, tg = lane & 3;
    const int wm = wid >> 2, wn = wid & 3;
    const int m0 = blockIdx.y << 7, n0 = blockIdx.x << 7;
    const int lrow = tid >> 1;
    const int lk   = (tid & 1) << 3;

    const float* Ap = A + (size_t)(m0 + lrow) * K + lk;
    const float* Wp = W + (size_t)(n0 + lrow) * K + lk;

    float acc[4][4][4] = {};
    float4 a0v = *(const float4*)Ap, a1v = *(const float4*)(Ap + 4);
    float4 b0v = *(const float4*)Wp, b1v = *(const float4*)(Wp + 4);
    {
        *(uint4*)&As[0][lrow][lk]     = PACK_HI(a0v, a1v);
        *(uint4*)&As[0][lrow][lk + 4] = PACK_LO(a0v, a1v);
        *(uint4*)&Bs[0][lrow][lk]     = PACK_HI(b0v, b1v);
        *(uint4*)&Bs[0][lrow][lk + 4] = PACK_LO(b0v, b1v);
    }
    __syncthreads();

    const int NT = K >> 4;
    for (int kt = 0; kt < NT; kt++) {
        if (kt + 1 < NT) {
            const float* Ap2 = Ap + (kt + 1) * 16;
            const float* Wp2 = Wp + (kt + 1) * 16;
            a0v = *(const float4*)Ap2; a1v = *(const float4*)(Ap2 + 4);
            b0v = *(const float4*)Wp2; b1v = *(const float4*)(Wp2 + 4);
        }
        const int buf = kt & 1;
        #pragma unroll
        for (int ks = 0; ks < 2; ks++) {
            const int kw = (ks << 3) + (tg << 1);
            unsigned bfr[4][2];
            #pragma unroll
            for (int ni = 0; ni < 4; ni++) {
                const int col = (wn << 5) + (ni << 3) + g;
                const uint2 bb = *(const uint2*)&Bs[buf][col][kw];
                bfr[ni][0] = bb.x; bfr[ni][1] = bb.y;
            }
            #pragma unroll
            for (int mi = 0; mi < 4; mi++) {
                const int row = (wm << 6) + (mi << 4);
                const uint2 a0 = *(const uint2*)&As[buf][row + g][kw];
                const uint2 a1 = *(const uint2*)&As[buf][row + g + 8][kw];
                unsigned af[4] = { a0.x, a1.x, a0.y, a1.y };
                #pragma unroll
                for (int ni = 0; ni < 4; ni++) mma8(acc[mi][ni], af, bfr[ni]);
            }
        }
        if (kt + 1 < NT) {
            *(uint4*)&As[buf ^ 1][lrow][lk]     = PACK_HI(a0v, a1v);
            *(uint4*)&As[buf ^ 1][lrow][lk + 4] = PACK_LO(a0v, a1v);
            *(uint4*)&Bs[buf ^ 1][lrow][lk]     = PACK_HI(b0v, b1v);
            *(uint4*)&Bs[buf ^ 1][lrow][lk + 4] = PACK_LO(b0v, b1v);
        }
        __syncthreads();
    }

    #pragma unroll
    for (int mi = 0; mi < 4; mi++) {
        const int r = m0 + (wm << 6) + (mi << 4) + g;
        #pragma unroll
        for (int ni = 0; ni < 4; ni++) {
            const int c = n0 + (wn << 5) + (ni << 3) + (tg << 1);
            float bx = 0.f, by = 0.f;
            if (bias) { bx = bias[c]; by = bias[c + 1]; }
            *(float2*)(C + (size_t)r * N + c) =
                make_float2(acc[mi][ni][0] + bx, acc[mi][ni][1] + by);
            *(float2*)(C + (size_t)(r + 8) * N + c) =
                make_float2(acc[mi][ni][2] + bx, acc[mi][ni][3] + by);
        }
    }
}

__global__ __launch_bounds__(256) void qkv_proj(
    const float* __restrict__ xq, const float* __restrict__ xkv,
    const float* __restrict__ Wq, const float* __restrict__ bq,
    const float* __restrict__ Wk,
    const float* __restrict__ Wv, const float* __restrict__ bv,
    float* __restrict__ q, float* __restrict__ k, float* __restrict__ v)
{
    const int z = blockIdx.z;
    const float* A    = (z == 0) ? xq : xkv;
    const float* W    = (z == 0) ? Wq : (z == 1 ? Wk : Wv);
    const float* bias = (z == 0) ? bq : (z == 1 ? nullptr : bv);
    float* C          = (z == 0) ? q  : (z == 1 ? k  : v);
    gemm_body(A, W, bias, C, B_ * SQ_, H_, H_);
}

__global__ __launch_bounds__(256) void out_proj(
    const float* __restrict__ ctx, const float* __restrict__ Wo,
    const float* __restrict__ bo, float* __restrict__ out)
{
    gemm_body(ctx, Wo, bo, out, B_ * SQ_, H_, H_);
}

// ---------------------------------------------------------------------------
// Flash v3: BQ=128, warp-local softmax, permuted-vectorized operand loads.
// Qs/Ks/Pw: [row][k-permuted 64 + pad] stride 68. Vs: transposed [e][kv] pair-
// packed, stride 68, so P@V B-fragments are single LDS.64.
// ---------------------------------------------------------------------------
constexpr int FLASH_SMEM = (128 * 68 + 64 * 68 + 64 * 68 + 8 * 16 * 68) * 4;

__global__ __launch_bounds__(256, 2) void flash_mma3(const float* __restrict__ mask)
{
    extern __shared__ unsigned fsm[];
    unsigned (*Qs)[68] = (unsigned(*)[68])fsm;                        // [128][68]
    unsigned (*Ks)[68] = (unsigned(*)[68])(fsm + 128 * 68);           // [64][68]
    unsigned (*Vs)[68] = (unsigned(*)[68])(fsm + 128 * 68 + 64 * 68); // [e][kv] packed
    unsigned* Pbase = fsm + 128 * 68 + 64 * 68 + 64 * 68;             // 8 x [16][68]

    const int tid = threadIdx.x, wid = tid >> 5, lane = tid & 31;
    const int g = lane >> 2, tg = lane & 3;
    const int r0 = wid << 4;
    const int q0 = blockIdx.x << 7, h = blockIdx.y, b = blockIdx.z;

    const float* Qg = g_q + (size_t)(b * SQ_ + q0) * H_ + h * HD_;
    const float* Kg = g_k + (size_t)b * SKV_ * H_ + h * HD_;
    const float* Vg = g_v + (size_t)b * SKV_ * H_ + h * HD_;
    const float* Mg = mask + (size_t)(b * SQ_ + q0) * SKV_;
    unsigned (*Pw)[68] = (unsigned(*)[68])(Pbase + wid * (16 * 68));

    // stage Q (tf32, pre-scaled 1/8), permuted pack
    #pragma unroll
    for (int i = 0; i < 4; i++) {
        const int idx = tid + (i << 8);
        const int r = idx >> 3, db = (idx & 7) << 3;
        float4 q0v = *(const float4*)(Qg + (size_t)r * H_ + db);
        float4 q1v = *(const float4*)(Qg + (size_t)r * H_ + db + 4);
        q0v.x *= 0.125f; q0v.y *= 0.125f; q0v.z *= 0.125f; q0v.w *= 0.125f;
        q1v.x *= 0.125f; q1v.y *= 0.125f; q1v.z *= 0.125f; q1v.w *= 0.125f;
        *(uint4*)&Qs[r][db]     = PACK_HI(q0v, q1v);
        *(uint4*)&Qs[r][db + 4] = PACK_LO(q0v, q1v);
    }

    float mr0 = -1e30f, mr1 = -1e30f, lr0 = 0.f, lr1 = 0.f;
    float o[8][4] = {};
    const int wp0 = ((tg & 1) << 2) | (tg >> 1);   // permuted word for col 2*tg

    for (int kv0 = 0; kv0 < SKV_; kv0 += 64) {
        __syncthreads();
        #pragma unroll
        for (int i = 0; i < 2; i++) {
            const int idx = tid + (i << 8);        // 0..511
            // K: row c, one 8-wide k-group
            const int c = idx >> 3, db = (idx & 7) << 3;
            const float4 k0v = *(const float4*)(Kg + (size_t)(kv0 + c) * H_ + db);
            const float4 k1v = *(const float4*)(Kg + (size_t)(kv0 + c) * H_ + db + 4);
            *(uint4*)&Ks[c][db]     = PACK_HI(k0v, k1v);
            *(uint4*)&Ks[c][db + 4] = PACK_LO(k0v, k1v);
            // V: column e, 8 kv rows (transposed pack)
            const int e = idx & 63, cb = (idx >> 6) << 3;
            float v0 = Vg[(size_t)(kv0 + cb + 0) * H_ + e];
            float v1 = Vg[(size_t)(kv0 + cb + 1) * H_ + e];
            float v2 = Vg[(size_t)(kv0 + cb + 2) * H_ + e];
            float v3 = Vg[(size_t)(kv0 + cb + 3) * H_ + e];
            float v4 = Vg[(size_t)(kv0 + cb + 4) * H_ + e];
            float v5 = Vg[(size_t)(kv0 + cb + 5) * H_ + e];
            float v6 = Vg[(size_t)(kv0 + cb + 6) * H_ + e];
            float v7 = Vg[(size_t)(kv0 + cb + 7) * H_ + e];
            *(uint4*)&Vs[e][cb]     = make_uint4(f2tf(v0), f2tf(v4), f2tf(v1), f2tf(v5));
            *(uint4*)&Vs[e][cb + 4] = make_uint4(f2tf(v2), f2tf(v6), f2tf(v3), f2tf(v7));
        }
        __syncthreads();

        // S = Q @ K^T
        float s[8][4] = {};
        #pragma unroll
        for (int ks = 0; ks < 8; ks++) {
            const int kw = (ks << 3) + (tg << 1);
            const uint2 a0 = *(const uint2*)&Qs[r0 + g][kw];
            const uint2 a1 = *(const uint2*)&Qs[r0 + g + 8][kw];
            unsigned af[4] = { a0.x, a1.x, a0.y, a1.y };
            #pragma unroll
            for (int ni = 0; ni < 8; ni++) {
                const uint2 bb = *(const uint2*)&Ks[(ni << 3) + g][kw];
                unsigned bf[2] = { bb.x, bb.y };
                mma8(s[ni], af, bf);
            }
        }

        // mask + warp-local row max
        float tm0 = -1e30f, tm1 = -1e30f;
        #pragma unroll
        for (int ni = 0; ni < 8; ni++) {
            const int c = (ni << 3) + (tg << 1);
            const float2 mv0 = *(const float2*)(Mg + (size_t)(r0 + g) * SKV_ + kv0 + c);
            const float2 mv1 = *(const float2*)(Mg + (size_t)(r0 + g + 8) * SKV_ + kv0 + c);
            s[ni][0] += (mv0.x - 1.f) * 10000.f;
            s[ni][1] += (mv0.y - 1.f) * 10000.f;
            s[ni][2] += (mv1.x - 1.f) * 10000.f;
            s[ni][3] += (mv1.y - 1.f) * 10000.f;
            tm0 = fmaxf(tm0, fmaxf(s[ni][0], s[ni][1]));
            tm1 = fmaxf(tm1, fmaxf(s[ni][2], s[ni][3]));
        }
        tm0 = fmaxf(tm0, __shfl_xor_sync(~0u, tm0, 1));
        tm0 = fmaxf(tm0, __shfl_xor_sync(~0u, tm0, 2));
        tm1 = fmaxf(tm1, __shfl_xor_sync(~0u, tm1, 1));
        tm1 = fmaxf(tm1, __shfl_xor_sync(~0u, tm1, 2));

        const float mn0 = fmaxf(mr0, tm0), mn1 = fmaxf(mr1, tm1);
        const float al0 = __expf(mr0 - mn0), al1 = __expf(mr1 - mn1);
        mr0 = mn0; mr1 = mn1;

        float ps0 = 0.f, ps1 = 0.f;
        #pragma unroll
        for (int ni = 0; ni < 8; ni++) {
            const float p00 = __expf(s[ni][0] - mn0), p01 = __expf(s[ni][1] - mn0);
            const float p10 = __expf(s[ni][2] - mn1), p11 = __expf(s[ni][3] - mn1);
            ps0 += p00 + p01; ps1 += p10 + p11;
            const int wbase = (ni << 3) + wp0;
            Pw[g    ][wbase]     = f2tf(p00);
            Pw[g    ][wbase + 2] = f2tf(p01);
            Pw[g + 8][wbase]     = f2tf(p10);
            Pw[g + 8][wbase + 2] = f2tf(p11);
            o[ni][0] *= al0; o[ni][1] *= al0; o[ni][2] *= al1; o[ni][3] *= al1;
        }
        ps0 += __shfl_xor_sync(~0u, ps0, 1); ps0 += __shfl_xor_sync(~0u, ps0, 2);
        ps1 += __shfl_xor_sync(~0u, ps1, 1); ps1 += __shfl_xor_sync(~0u, ps1, 2);
        lr0 = lr0 * al0 + ps0;
        lr1 = lr1 * al1 + ps1;
        __syncwarp();

        // O += P @ V
        #pragma unroll
        for (int ks = 0; ks < 8; ks++) {
            const int kw = (ks << 3) + (tg << 1);
            const uint2 a0 = *(const uint2*)&Pw[g][kw];
            const uint2 a1 = *(const uint2*)&Pw[g + 8][kw];
            unsigned af[4] = { a0.x, a1.x, a0.y, a1.y };
            #pragma unroll
            for (int ni = 0; ni < 8; ni++) {
                const uint2 bb = *(const uint2*)&Vs[(ni << 3) + g][kw];
                unsigned bf[2] = { bb.x, bb.y };
                mma8(o[ni], af, bf);
            }
        }
        __syncwarp();
    }

    float* Og = g_ctx + (size_t)(b * SQ_ + q0) * H_ + h * HD_;
    const float inv0 = 1.f / lr0, inv1 = 1.f / lr1;
    #pragma unroll
    for (int ni = 0; ni < 8; ni++) {
        const int c = (ni << 3) + (tg << 1);
        *(float2*)(Og + (size_t)(r0 + g) * H_ + c) =
            make_float2(o[ni][0] * inv0, o[ni][1] * inv0);
        *(float2*)(Og + (size_t)(r0 + g + 8) * H_ + c) =
            make_float2(o[ni][2] * inv1, o[ni][3] * inv1);
    }
}

// ---------------------------------------------------------------------------
extern "C" void kernel_launch(void* const* d_in, const int* in_sizes, int n_in,
                              void* d_out, int out_size)
{
    const float* xq  = (const float*)d_in[0];
    const float* xkv = (const float*)d_in[1];
    const float* msk = (const float*)d_in[2];
    const float* Wq  = (const float*)d_in[3];
    const float* bq  = (const float*)d_in[4];
    const float* Wk  = (const float*)d_in[5];
    const float* Wv  = (const float*)d_in[6];
    const float* bv  = (const float*)d_in[7];
    const float* Wo  = (const float*)d_in[8];
    const float* bo  = (const float*)d_in[9];
    float* out = (float*)d_out;

    void *pq, *pk, *pv, *pc;
    cudaGetSymbolAddress(&pq, g_q);
    cudaGetSymbolAddress(&pk, g_k);
    cudaGetSymbolAddress(&pv, g_v);
    cudaGetSymbolAddress(&pc, g_ctx);

    const dim3 blk(256);

    qkv_proj<<<dim3(H_ / 128, (B_ * SQ_) / 128, 3), blk>>>(
        xq, xkv, Wq, bq, Wk, Wv, bv, (float*)pq, (float*)pk, (float*)pv);

    cudaFuncSetAttribute(flash_mma3, cudaFuncAttributeMaxDynamicSharedMemorySize, FLASH_SMEM);
    flash_mma3<<<dim3(SQ_ / 128, NH_, B_), blk, FLASH_SMEM>>>(msk);

    out_proj<<<dim3(H_ / 128, (B_ * SQ_) / 128), blk>>>((const float*)pc, Wo, bo, out);
}

// round 8
// speedup vs baseline: 1.2342x; 1.2342x over previous
#include <cuda_runtime.h>

constexpr int B_   = 2;
constexpr int SQ_  = 2048;
constexpr int SKV_ = 2048;
constexpr int H_   = 1024;
constexpr int NH_  = 16;
constexpr int HD_  = 64;
constexpr int NSM_ = 148;          // GB300 has 152; 148 is safe/portable
constexpr int PGRID = NSM_ * 2;    // 2 CTAs/SM resident for both kernels

__device__ float g_q[(size_t)B_ * SQ_ * H_];
__device__ float g_k[(size_t)B_ * SKV_ * H_];
__device__ float g_v[(size_t)B_ * SKV_ * H_];
__device__ float g_ctx[(size_t)B_ * SQ_ * H_];

__device__ __forceinline__ unsigned f2tf(float f) {
    unsigned u; asm("cvt.rna.tf32.f32 %0, %1;" : "=r"(u) : "f"(f)); return u;
}
__device__ __forceinline__ void mma8(float d[4], const unsigned a[4], const unsigned b[2]) {
    asm volatile(
        "mma.sync.aligned.m16n8k8.row.col.f32.tf32.tf32.f32 "
        "{%0,%1,%2,%3},{%4,%5,%6,%7},{%8,%9},{%0,%1,%2,%3};"
        : "+f"(d[0]), "+f"(d[1]), "+f"(d[2]), "+f"(d[3])
        : "r"(a[0]), "r"(a[1]), "r"(a[2]), "r"(a[3]), "r"(b[0]), "r"(b[1]));
}

// ---------------- projection GEMM tile (R5-proven inner loop) --------------
__device__ __forceinline__ void gemm_tile(
    const float* __restrict__ A, const float* __restrict__ W,
    const float* __restrict__ bias, float* __restrict__ C,
    int m0, int n0, int K, int N,
    unsigned (*As)[128][20], unsigned (*Bs)[128][20])
{
    const int tid = threadIdx.x;
    const int wid = tid >> 5, lane = tid & 31;
    const int g = lane >> 2, tg = lane & 3;
    const int wm = wid >> 2, wn = wid & 3;
    const int lrow = tid >> 1;
    const int lk   = (tid & 1) << 3;

    const float* Ap = A + (size_t)(m0 + lrow) * K + lk;
    const float* Wp = W + (size_t)(n0 + lrow) * K + lk;

    float acc[4][4][4] = {};
    float4 a0v = *(const float4*)Ap, a1v = *(const float4*)(Ap + 4);
    float4 b0v = *(const float4*)Wp, b1v = *(const float4*)(Wp + 4);
    {
        unsigned* ar = &As[0][lrow][lk];
        ar[0]=f2tf(a0v.x); ar[1]=f2tf(a0v.y); ar[2]=f2tf(a0v.z); ar[3]=f2tf(a0v.w);
        ar[4]=f2tf(a1v.x); ar[5]=f2tf(a1v.y); ar[6]=f2tf(a1v.z); ar[7]=f2tf(a1v.w);
        unsigned* br = &Bs[0][lrow][lk];
        br[0]=f2tf(b0v.x); br[1]=f2tf(b0v.y); br[2]=f2tf(b0v.z); br[3]=f2tf(b0v.w);
        br[4]=f2tf(b1v.x); br[5]=f2tf(b1v.y); br[6]=f2tf(b1v.z); br[7]=f2tf(b1v.w);
    }
    __syncthreads();

    const int NT = K >> 4;                 // 64 (even -> buffer parity safe)
    for (int kt = 0; kt < NT; kt++) {
        if (kt + 1 < NT) {
            const float* Ap2 = Ap + (kt + 1) * 16;
            const float* Wp2 = Wp + (kt + 1) * 16;
            a0v = *(const float4*)Ap2; a1v = *(const float4*)(Ap2 + 4);
            b0v = *(const float4*)Wp2; b1v = *(const float4*)(Wp2 + 4);
        }
        const int buf = kt & 1;
        #pragma unroll
        for (int ks = 0; ks < 2; ks++) {
            const int kk = ks << 3;
            unsigned bfr[4][2];
            #pragma unroll
            for (int ni = 0; ni < 4; ni++) {
                const int col = (wn << 5) + (ni << 3) + g;
                bfr[ni][0] = Bs[buf][col][kk + tg];
                bfr[ni][1] = Bs[buf][col][kk + tg + 4];
            }
            #pragma unroll
            for (int mi = 0; mi < 4; mi++) {
                const int row = (wm << 6) + (mi << 4);
                unsigned af[4];
                af[0] = As[buf][row + g    ][kk + tg];
                af[1] = As[buf][row + g + 8][kk + tg];
                af[2] = As[buf][row + g    ][kk + tg + 4];
                af[3] = As[buf][row + g + 8][kk + tg + 4];
                #pragma unroll
                for (int ni = 0; ni < 4; ni++) mma8(acc[mi][ni], af, bfr[ni]);
            }
        }
        if (kt + 1 < NT) {
            unsigned* ar = &As[buf ^ 1][lrow][lk];
            ar[0]=f2tf(a0v.x); ar[1]=f2tf(a0v.y); ar[2]=f2tf(a0v.z); ar[3]=f2tf(a0v.w);
            ar[4]=f2tf(a1v.x); ar[5]=f2tf(a1v.y); ar[6]=f2tf(a1v.z); ar[7]=f2tf(a1v.w);
            unsigned* br = &Bs[buf ^ 1][lrow][lk];
            br[0]=f2tf(b0v.x); br[1]=f2tf(b0v.y); br[2]=f2tf(b0v.z); br[3]=f2tf(b0v.w);
            br[4]=f2tf(b1v.x); br[5]=f2tf(b1v.y); br[6]=f2tf(b1v.z); br[7]=f2tf(b1v.w);
        }
        __syncthreads();
    }

    #pragma unroll
    for (int mi = 0; mi < 4; mi++) {
        const int r = m0 + (wm << 6) + (mi << 4) + g;
        #pragma unroll
        for (int ni = 0; ni < 4; ni++) {
            const int c = n0 + (wn << 5) + (ni << 3) + (tg << 1);
            float bx = 0.f, by = 0.f;
            if (bias) { bx = bias[c]; by = bias[c + 1]; }
            *(float2*)(C + (size_t)r * N + c) =
                make_float2(acc[mi][ni][0] + bx, acc[mi][ni][1] + by);
            *(float2*)(C + (size_t)(r + 8) * N + c) =
                make_float2(acc[mi][ni][2] + bx, acc[mi][ni][3] + by);
        }
    }
}

// Persistent fused QKV: 768 tiles (z:3, m:32, n:8) strided over PGRID CTAs.
__global__ __launch_bounds__(256) void qkv_proj(
    const float* __restrict__ xq, const float* __restrict__ xkv,
    const float* __restrict__ Wq, const float* __restrict__ bq,
    const float* __restrict__ Wk,
    const float* __restrict__ Wv, const float* __restrict__ bv,
    float* __restrict__ q, float* __restrict__ k, float* __restrict__ v)
{
    __shared__ unsigned As[2][128][20];
    __shared__ unsigned Bs[2][128][20];
    constexpr int TILES = 3 * 32 * 8;
    for (int t = blockIdx.x; t < TILES; t += PGRID) {
        const int z = t >> 8, rem = t & 255;
        const int m0 = (rem >> 3) << 7, n0 = (rem & 7) << 7;
        const float* A    = (z == 0) ? xq : xkv;
        const float* W    = (z == 0) ? Wq : (z == 1 ? Wk : Wv);
        const float* bias = (z == 0) ? bq : (z == 1 ? nullptr : bv);
        float* C          = (z == 0) ? q  : (z == 1 ? k  : v);
        gemm_tile(A, W, bias, C, m0, n0, H_, H_, As, Bs);
    }
}

__global__ __launch_bounds__(256) void out_proj(
    const float* __restrict__ ctx, const float* __restrict__ Wo,
    const float* __restrict__ bo, float* __restrict__ out)
{
    __shared__ unsigned As[2][128][20];
    __shared__ unsigned Bs[2][128][20];
    gemm_tile(ctx, Wo, bo, out, blockIdx.y << 7, blockIdx.x << 7, H_, H_, As, Bs);
}

// ---------------------------------------------------------------------------
// Flash v2 (R5-proven), persistent over 512 items (b,h,q-tile).
// ---------------------------------------------------------------------------
constexpr int FLASH_SMEM = (128 * 68 + 64 * 68 + 64 * 72 + 8 * 16 * 68) * 4;

__global__ __launch_bounds__(256, 2) void flash_mma2(const float* __restrict__ mask)
{
    extern __shared__ unsigned fsm[];
    unsigned (*Qs)[68] = (unsigned(*)[68])fsm;
    unsigned (*Ks)[68] = (unsigned(*)[68])(fsm + 128 * 68);
    unsigned (*Vs)[72] = (unsigned(*)[72])(fsm + 128 * 68 + 64 * 68);
    unsigned* Pbase = fsm + 128 * 68 + 64 * 68 + 64 * 72;

    const int tid = threadIdx.x, wid = tid >> 5, lane = tid & 31;
    const int g = lane >> 2, tg = lane & 3;
    const int r0 = wid << 4;
    unsigned (*Pw)[68] = (unsigned(*)[68])(Pbase + wid * (16 * 68));

    constexpr int ITEMS = (SQ_ / 128) * NH_ * B_;   // 16*16*2 = 512
    for (int it = blockIdx.x; it < ITEMS; it += PGRID) {
        const int q0 = (it & 15) << 7;
        const int h  = (it >> 4) & 15;
        const int b  = it >> 8;

        const float* Qg = g_q + (size_t)(b * SQ_ + q0) * H_ + h * HD_;
        const float* Kg = g_k + (size_t)b * SKV_ * H_ + h * HD_;
        const float* Vg = g_v + (size_t)b * SKV_ * H_ + h * HD_;
        const float* Mg = mask + (size_t)(b * SQ_ + q0) * SKV_;

        __syncthreads();   // prior item fully done with Qs before restage
        #pragma unroll
        for (int i = 0; i < 8; i++) {
            const int idx = tid + (i << 8);
            const int r = idx >> 4, d = (idx & 15) << 2;
            const float4 v = *(const float4*)(Qg + (size_t)r * H_ + d);
            *(uint4*)&Qs[r][d] = make_uint4(f2tf(v.x * 0.125f), f2tf(v.y * 0.125f),
                                            f2tf(v.z * 0.125f), f2tf(v.w * 0.125f));
        }

        float mr0 = -1e30f, mr1 = -1e30f, lr0 = 0.f, lr1 = 0.f;
        float o[8][4] = {};

        for (int kv0 = 0; kv0 < SKV_; kv0 += 64) {
            __syncthreads();
            #pragma unroll
            for (int i = 0; i < 4; i++) {
                const int idx = tid + (i << 8);
                const int c = idx >> 4, d = (idx & 15) << 2;
                const float4 kv = *(const float4*)(Kg + (size_t)(kv0 + c) * H_ + d);
                *(uint4*)&Ks[c][d] = make_uint4(f2tf(kv.x), f2tf(kv.y), f2tf(kv.z), f2tf(kv.w));
                const float4 vv = *(const float4*)(Vg + (size_t)(kv0 + c) * H_ + d);
                *(uint4*)&Vs[c][d] = make_uint4(f2tf(vv.x), f2tf(vv.y), f2tf(vv.z), f2tf(vv.w));
            }
            __syncthreads();

            float s[8][4] = {};
            #pragma unroll
            for (int ks = 0; ks < 8; ks++) {
                const int kk = ks << 3;
                unsigned af[4];
                af[0] = Qs[r0 + g    ][kk + tg];
                af[1] = Qs[r0 + g + 8][kk + tg];
                af[2] = Qs[r0 + g    ][kk + tg + 4];
                af[3] = Qs[r0 + g + 8][kk + tg + 4];
                #pragma unroll
                for (int ni = 0; ni < 8; ni++) {
                    const int c = (ni << 3) + g;
                    unsigned bf[2] = { Ks[c][kk + tg], Ks[c][kk + tg + 4] };
                    mma8(s[ni], af, bf);
                }
            }

            float tm0 = -1e30f, tm1 = -1e30f;
            #pragma unroll
            for (int ni = 0; ni < 8; ni++) {
                const int c = (ni << 3) + (tg << 1);
                const float2 mv0 = *(const float2*)(Mg + (size_t)(r0 + g) * SKV_ + kv0 + c);
                const float2 mv1 = *(const float2*)(Mg + (size_t)(r0 + g + 8) * SKV_ + kv0 + c);
                s[ni][0] += (mv0.x - 1.f) * 10000.f;
                s[ni][1] += (mv0.y - 1.f) * 10000.f;
                s[ni][2] += (mv1.x - 1.f) * 10000.f;
                s[ni][3] += (mv1.y - 1.f) * 10000.f;
                tm0 = fmaxf(tm0, fmaxf(s[ni][0], s[ni][1]));
                tm1 = fmaxf(tm1, fmaxf(s[ni][2], s[ni][3]));
            }
            tm0 = fmaxf(tm0, __shfl_xor_sync(~0u, tm0, 1));
            tm0 = fmaxf(tm0, __shfl_xor_sync(~0u, tm0, 2));
            tm1 = fmaxf(tm1, __shfl_xor_sync(~0u, tm1, 1));
            tm1 = fmaxf(tm1, __shfl_xor_sync(~0u, tm1, 2));

            const float mn0 = fmaxf(mr0, tm0), mn1 = fmaxf(mr1, tm1);
            const float al0 = __expf(mr0 - mn0), al1 = __expf(mr1 - mn1);
            mr0 = mn0; mr1 = mn1;

            float ps0 = 0.f, ps1 = 0.f;
            #pragma unroll
            for (int ni = 0; ni < 8; ni++) {
                const int c = (ni << 3) + (tg << 1);
                const float p00 = __expf(s[ni][0] - mn0), p01 = __expf(s[ni][1] - mn0);
                const float p10 = __expf(s[ni][2] - mn1), p11 = __expf(s[ni][3] - mn1);
                ps0 += p00 + p01; ps1 += p10 + p11;
                Pw[g    ][c] = f2tf(p00); Pw[g    ][c + 1] = f2tf(p01);
                Pw[g + 8][c] = f2tf(p10); Pw[g + 8][c + 1] = f2tf(p11);
                o[ni][0] *= al0; o[ni][1] *= al0; o[ni][2] *= al1; o[ni][3] *= al1;
            }
            ps0 += __shfl_xor_sync(~0u, ps0, 1); ps0 += __shfl_xor_sync(~0u, ps0, 2);
            ps1 += __shfl_xor_sync(~0u, ps1, 1); ps1 += __shfl_xor_sync(~0u, ps1, 2);
            lr0 = lr0 * al0 + ps0;
            lr1 = lr1 * al1 + ps1;
            __syncwarp();

            #pragma unroll
            for (int ks = 0; ks < 8; ks++) {
                const int kk = ks << 3;
                unsigned af[4];
                af[0] = Pw[g    ][kk + tg];
                af[1] = Pw[g + 8][kk + tg];
                af[2] = Pw[g    ][kk + tg + 4];
                af[3] = Pw[g + 8][kk + tg + 4];
                #pragma unroll
                for (int ni = 0; ni < 8; ni++) {
                    const int e = (ni << 3) + g;
                    unsigned bf[2] = { Vs[kk + tg][e], Vs[kk + tg + 4][e] };
                    mma8(o[ni], af, bf);
                }
            }
            __syncwarp();
        }

        float* Og = g_ctx + (size_t)(b * SQ_ + q0) * H_ + h * HD_;
        const float inv0 = 1.f / lr0, inv1 = 1.f / lr1;
        #pragma unroll
        for (int ni = 0; ni < 8; ni++) {
            const int c = (ni << 3) + (tg << 1);
            *(float2*)(Og + (size_t)(r0 + g) * H_ + c) =
                make_float2(o[ni][0] * inv0, o[ni][1] * inv0);
            *(float2*)(Og + (size_t)(r0 + g + 8) * H_ + c) =
                make_float2(o[ni][2] * inv1, o[ni][3] * inv1);
        }
    }
}

// ---------------------------------------------------------------------------
extern "C" void kernel_launch(void* const* d_in, const int* in_sizes, int n_in,
                              void* d_out, int out_size)
{
    const float* xq  = (const float*)d_in[0];
    const float* xkv = (const float*)d_in[1];
    const float* msk = (const float*)d_in[2];
    const float* Wq  = (const float*)d_in[3];
    const float* bq  = (const float*)d_in[4];
    const float* Wk  = (const float*)d_in[5];
    const float* Wv  = (const float*)d_in[6];
    const float* bv  = (const float*)d_in[7];
    const float* Wo  = (const float*)d_in[8];
    const float* bo  = (const float*)d_in[9];
    float* out = (float*)d_out;

    void *pq, *pk, *pv, *pc;
    cudaGetSymbolAddress(&pq, g_q);
    cudaGetSymbolAddress(&pk, g_k);
    cudaGetSymbolAddress(&pv, g_v);
    cudaGetSymbolAddress(&pc, g_ctx);

    const dim3 blk(256);

    qkv_proj<<<dim3(PGRID), blk>>>(
        xq, xkv, Wq, bq, Wk, Wv, bv, (float*)pq, (float*)pk, (float*)pv);

    cudaFuncSetAttribute(flash_mma2, cudaFuncAttributeMaxDynamicSharedMemorySize, FLASH_SMEM);
    flash_mma2<<<dim3(PGRID), blk, FLASH_SMEM>>>(msk);

    out_proj<<<dim3(H_ / 128, (B_ * SQ_) / 128), blk>>>((const float*)pc, Wo, bo, out);
}